// round 3
// baseline (speedup 1.0000x reference)
#include <cuda_runtime.h>

#define BATCH   8
#define CH      512
#define SEQ     1024          // H*W = 32*32
#define NH      8
#define HD      64
#define QKV_DIM 1536          // 3*CH

// Scratch (allocation-free rule: __device__ globals)
__device__ float g_qkv[BATCH * SEQ * QKV_DIM];   // [b][n][3C]  (Q at j, K at C+j, V at 2C+j)
__device__ float g_att[BATCH * SEQ * CH];        // [b][n][C]

// ---------------------------------------------------------------------------
// Kernel 1: QKV projection.  qkv[b][n][j] = sum_c x[b][c][n] * Wqkv[j][c] + bqkv[j]
// A is consumed as x[b][k][m] (m contiguous -> coalesced), i.e. transpose fused.
// Tiles: 64(m) x 64(j) x 16(k); 16x16 threads; 4x4 micro-tile.
// ---------------------------------------------------------------------------
__global__ void qkv_gemm(const float* __restrict__ x,
                         const float* __restrict__ Wqkv,
                         const float* __restrict__ bqkv)
{
    const int b  = blockIdx.z;
    const int m0 = blockIdx.y * 64;   // token tile
    const int j0 = blockIdx.x * 64;   // qkv-feature tile
    const int tx = threadIdx.x;       // 0..15 -> j
    const int ty = threadIdx.y;       // 0..15 -> m
    const int tid = ty * 16 + tx;

    __shared__ float As[16 * 64];     // [kk][mm]
    __shared__ float Bs[16 * 68];     // [kk][nn] padded (68: float4-aligned rows)

    const float* xb = x + (size_t)b * CH * SEQ;

    float acc[4][4];
    #pragma unroll
    for (int i = 0; i < 4; i++)
        #pragma unroll
        for (int j = 0; j < 4; j++) acc[i][j] = 0.f;

    for (int k0 = 0; k0 < CH; k0 += 16) {
        #pragma unroll
        for (int t = 0; t < 4; t++) {         // A: 1024 floats, coalesced along n
            int idx = t * 256 + tid;
            int kk = idx >> 6, mm = idx & 63;
            As[kk * 64 + mm] = xb[(size_t)(k0 + kk) * SEQ + m0 + mm];
        }
        #pragma unroll
        for (int t = 0; t < 4; t++) {         // B: Wqkv[j][c], c contiguous
            int idx = t * 256 + tid;
            int kk = idx & 15, nn = idx >> 4;
            Bs[kk * 68 + nn] = Wqkv[(size_t)(j0 + nn) * CH + k0 + kk];
        }
        __syncthreads();
        #pragma unroll
        for (int kk = 0; kk < 16; kk++) {
            float4 a  = *(const float4*)&As[kk * 64 + ty * 4];
            float4 bb = *(const float4*)&Bs[kk * 68 + tx * 4];
            float av[4] = {a.x, a.y, a.z, a.w};
            float bv[4] = {bb.x, bb.y, bb.z, bb.w};
            #pragma unroll
            for (int i = 0; i < 4; i++)
                #pragma unroll
                for (int j = 0; j < 4; j++)
                    acc[i][j] += av[i] * bv[j];
        }
        __syncthreads();
    }

    float* outb = g_qkv + (size_t)b * SEQ * QKV_DIM;
    float4 bias = *(const float4*)&bqkv[j0 + tx * 4];
    #pragma unroll
    for (int i = 0; i < 4; i++) {
        int m = m0 + ty * 4 + i;
        float4 r;
        r.x = acc[i][0] + bias.x;
        r.y = acc[i][1] + bias.y;
        r.z = acc[i][2] + bias.z;
        r.w = acc[i][3] + bias.w;
        *(float4*)&outb[(size_t)m * QKV_DIM + j0 + tx * 4] = r;  // coalesced over tx
    }
}

// ---------------------------------------------------------------------------
// Kernel 2: causal flash attention, one thread = one query row.
// grid (8 q-tiles of 128, 64 b*h), block 128.
// K/V staged in SMEM 32x64 blocks; all threads read keys in lockstep -> LDS broadcast.
// Causal: q-tile qt only visits key blocks [0, (qt+1)*128) -> half the FLOPs.
// ---------------------------------------------------------------------------
__global__ void attn_kernel()
{
    const int qt  = blockIdx.x;           // 0..7
    const int bh  = blockIdx.y;           // 0..63
    const int b   = bh >> 3;
    const int h   = bh & 7;
    const int tid = threadIdx.x;          // 0..127
    const int i   = qt * 128 + tid;       // global query row

    const float* qkvb = g_qkv + (size_t)b * SEQ * QKV_DIM;
    const float scale = 0.125f;           // HD^-0.5

    __shared__ float Ks[32 * 64];
    __shared__ float Vs[32 * 64];

    float4 q4[16], o4[16];
    {
        const float4* qrow = (const float4*)(qkvb + (size_t)i * QKV_DIM + h * HD);
        #pragma unroll
        for (int d = 0; d < 16; d++) { q4[d] = qrow[d]; o4[d] = make_float4(0.f, 0.f, 0.f, 0.f); }
    }

    float mrun = -1e30f, l = 0.f;

    const int nkb = (qt + 1) * 4;         // key blocks of 32
    for (int kb = 0; kb < nkb; kb++) {
        const int k0 = kb * 32;
        #pragma unroll
        for (int t = 0; t < 4; t++) {     // cooperative K/V load (float4, coalesced)
            int f   = t * 128 + tid;      // 0..511 float4 slots
            int row = f >> 4;
            int c4  = f & 15;
            const float* base = qkvb + (size_t)(k0 + row) * QKV_DIM + h * HD;
            ((float4*)Ks)[row * 16 + c4] = ((const float4*)(base + CH))[c4];
            ((float4*)Vs)[row * 16 + c4] = ((const float4*)(base + 2 * CH))[c4];
        }
        __syncthreads();

        float s[32];
        #pragma unroll
        for (int j = 0; j < 32; j++) {
            const float4* kr = (const float4*)(Ks + j * 64);
            float4 acc = make_float4(0.f, 0.f, 0.f, 0.f);
            #pragma unroll
            for (int d = 0; d < 16; d++) {
                float4 kv = kr[d];                       // broadcast LDS
                acc.x += q4[d].x * kv.x;
                acc.y += q4[d].y * kv.y;
                acc.z += q4[d].z * kv.z;
                acc.w += q4[d].w * kv.w;
            }
            float sv = (acc.x + acc.y) + (acc.z + acc.w);
            s[j] = (k0 + j <= i) ? sv * scale : -1e30f;  // causal mask
        }

        float mb = s[0];
        #pragma unroll
        for (int j = 1; j < 32; j++) mb = fmaxf(mb, s[j]);
        float mnew  = fmaxf(mrun, mb);
        float alpha = __expf(mrun - mnew);               // first block: exp(-huge)=0
        l *= alpha;
        #pragma unroll
        for (int d = 0; d < 16; d++) {
            o4[d].x *= alpha; o4[d].y *= alpha; o4[d].z *= alpha; o4[d].w *= alpha;
        }
        #pragma unroll
        for (int j = 0; j < 32; j++) {
            float p = __expf(s[j] - mnew);               // masked: exp(-huge)=0
            l += p;
            const float4* vr = (const float4*)(Vs + j * 64);
            #pragma unroll
            for (int d = 0; d < 16; d++) {
                float4 vv = vr[d];                       // broadcast LDS
                o4[d].x += p * vv.x;
                o4[d].y += p * vv.y;
                o4[d].z += p * vv.z;
                o4[d].w += p * vv.w;
            }
        }
        mrun = mnew;
        __syncthreads();
    }

    const float inv = 1.f / l;
    float* orow = g_att + ((size_t)b * SEQ + i) * CH + h * HD;
    #pragma unroll
    for (int d = 0; d < 16; d++) {
        float4 r = make_float4(o4[d].x * inv, o4[d].y * inv, o4[d].z * inv, o4[d].w * inv);
        ((float4*)orow)[d] = r;
    }
}

// ---------------------------------------------------------------------------
// Kernel 3: output projection + fused transpose to NCHW.
// out[b][j][n] = sum_c g_att[b][n][c] * Wproj[j][c] + bproj[j]
// Token index mapped to tx so the [b][j][n] store is coalesced.
// ---------------------------------------------------------------------------
__global__ void proj_gemm(const float* __restrict__ Wp,
                          const float* __restrict__ bp,
                          float* __restrict__ out)
{
    const int b  = blockIdx.z;
    const int m0 = blockIdx.x * 64;   // token tile
    const int j0 = blockIdx.y * 64;   // out-channel tile
    const int tx = threadIdx.x;       // -> m (tokens, contiguous in output)
    const int ty = threadIdx.y;       // -> j
    const int tid = ty * 16 + tx;

    __shared__ float As[16 * 68];     // [kk][mm] padded
    __shared__ float Bs[16 * 68];     // [kk][nn] padded

    const float* A = g_att + (size_t)b * SEQ * CH;

    float acc[4][4];                  // [jj][mi]
    #pragma unroll
    for (int i = 0; i < 4; i++)
        #pragma unroll
        for (int j = 0; j < 4; j++) acc[i][j] = 0.f;

    for (int k0 = 0; k0 < CH; k0 += 16) {
        #pragma unroll
        for (int t = 0; t < 4; t++) {
            int idx = t * 256 + tid;
            int mm = idx >> 4, kk = idx & 15;
            As[kk * 68 + mm] = A[(size_t)(m0 + mm) * CH + k0 + kk];
            Bs[kk * 68 + mm] = Wp[(size_t)(j0 + mm) * CH + k0 + kk];
        }
        __syncthreads();
        #pragma unroll
        for (int kk = 0; kk < 16; kk++) {
            float4 a  = *(const float4*)&As[kk * 68 + tx * 4];
            float4 bb = *(const float4*)&Bs[kk * 68 + ty * 4];
            float av[4] = {a.x, a.y, a.z, a.w};
            float bv[4] = {bb.x, bb.y, bb.z, bb.w};
            #pragma unroll
            for (int jj = 0; jj < 4; jj++)
                #pragma unroll
                for (int mi = 0; mi < 4; mi++)
                    acc[jj][mi] += bv[jj] * av[mi];
        }
        __syncthreads();
    }

    float* outb = out + (size_t)b * CH * SEQ;
    #pragma unroll
    for (int jj = 0; jj < 4; jj++) {
        int j = j0 + ty * 4 + jj;
        float bias = bp[j];
        float4 r;
        r.x = acc[jj][0] + bias;
        r.y = acc[jj][1] + bias;
        r.z = acc[jj][2] + bias;
        r.w = acc[jj][3] + bias;
        *(float4*)&outb[(size_t)j * SEQ + m0 + tx * 4] = r;   // coalesced over tx
    }
}

// ---------------------------------------------------------------------------
extern "C" void kernel_launch(void* const* d_in, const int* in_sizes, int n_in,
                              void* d_out, int out_size)
{
    const float* x    = (const float*)d_in[0];   // (8, 512, 32, 32)
    const float* Wqkv = (const float*)d_in[1];   // (1536, 512)
    const float* bqkv = (const float*)d_in[2];   // (1536,)
    const float* Wp   = (const float*)d_in[3];   // (512, 512)
    const float* bp   = (const float*)d_in[4];   // (512,)
    float* out = (float*)d_out;                  // (8, 512, 32, 32)

    (void)in_sizes; (void)n_in; (void)out_size;

    qkv_gemm<<<dim3(QKV_DIM / 64, SEQ / 64, BATCH), dim3(16, 16)>>>(x, Wqkv, bqkv);
    attn_kernel<<<dim3(SEQ / 128, BATCH * NH), 128>>>();
    proj_gemm<<<dim3(SEQ / 64, CH / 64, BATCH), dim3(16, 16)>>>(Wp, bp, out);
}